// round 14
// baseline (speedup 1.0000x reference)
#include <cuda_runtime.h>
#include <cuda_fp16.h>
#include <cstdint>

// ============================================================================
// out[8192,1536] = x[8192,3072] @ (mask.T * w)[3072,1536] + b
// R14: SMEM-FREE GEMM. Both A and B pre-packed fragment-major in gmem;
//      mainloop is pure LDG.128 + mma.sync per warp with register double
//      buffering. No cp.async, no __syncthreads, no convoys.
// ============================================================================

static constexpr int MDIM = 8192;
static constexpr int NDIM = 1536;
static constexpr int KDIM = 3072;

static constexpr int TM = 256;
static constexpr int TN = 64;
static constexpr int TILES_N = NDIM / TN;   // 24
static constexpr int TILES_M = MDIM / TM;   // 32
static constexpr int KB16 = KDIM / 16;      // 192 16-k fragment blocks

// Prep kernel grid split
static constexpr int CONV_BLOCKS = (MDIM / 16) * KB16 / 8;   // 12288
static constexpr int BPACK_KT = KDIM / 64;                   // 48
static constexpr int BPACK_NT = NDIM / 32;                   // 48
static constexpr int BPACK_BLOCKS = BPACK_KT * BPACK_NT;     // 2304

// A fragment-major: frag (mb, kb) -> 32 lanes x 16B
__device__ uint4 g_xfrag[(size_t)(MDIM / 16) * KB16 * 32];
// B fragment-major: frag (nb, kb) -> 32 lanes x 16B
//   lane l: nn = nb*16 + l/4, kk = kb*16 + (l%4)*2
//   .x = half2(B[kk][nn],   B[kk+1][nn])    .y = half2(B[kk+8][nn], B[kk+9][nn])
//   .z = same with nn+8 (k 0-7)             .w = same with nn+8 (k 8-15)
__device__ uint4 g_Bfrag[(size_t)(NDIM / 16) * KB16 * 32];

// ---------------------------------------------------------------------------
#define MMA16816(d, a0, a1, a2, a3, b0, b1) \
    asm volatile("mma.sync.aligned.m16n8k16.row.col.f32.f16.f16.f32 " \
                 "{%0,%1,%2,%3}, {%4,%5,%6,%7}, {%8,%9}, {%0,%1,%2,%3};" \
                 : "+f"((d)[0]), "+f"((d)[1]), "+f"((d)[2]), "+f"((d)[3]) \
                 : "r"(a0), "r"(a1), "r"(a2), "r"(a3), "r"(b0), "r"(b1))

// ---------------------------------------------------------------------------
// Fused prep kernel:
//  blocks [0, CONV_BLOCKS): x -> A fragments (one warp per 16x16 fragment)
//  blocks [CONV_BLOCKS, +BPACK_BLOCKS): mask*w^T -> B fragments
// ---------------------------------------------------------------------------
__global__ void __launch_bounds__(256) prep_kernel(const float* __restrict__ x,
                                                   const float* __restrict__ w,
                                                   const float* __restrict__ mask) {
    if (blockIdx.x < CONV_BLOCKS) {
        int f = blockIdx.x * 8 + (threadIdx.x >> 5);   // fragment id
        int lane = threadIdx.x & 31;
        int mb = f / KB16;
        int kb = f - mb * KB16;
        int r = mb * 16 + (lane >> 2);
        int c = kb * 16 + (lane & 3) * 2;
        const float* p00 = x + (size_t)r * KDIM + c;
        float2 v00 = *reinterpret_cast<const float2*>(p00);
        float2 v10 = *reinterpret_cast<const float2*>(p00 + 8 * KDIM);
        float2 v01 = *reinterpret_cast<const float2*>(p00 + 8);
        float2 v11 = *reinterpret_cast<const float2*>(p00 + 8 * KDIM + 8);
        __half2 h0 = __floats2half2_rn(v00.x, v00.y);
        __half2 h1 = __floats2half2_rn(v10.x, v10.y);
        __half2 h2 = __floats2half2_rn(v01.x, v01.y);
        __half2 h3 = __floats2half2_rn(v11.x, v11.y);
        uint4 u;
        u.x = *reinterpret_cast<uint32_t*>(&h0);
        u.y = *reinterpret_cast<uint32_t*>(&h1);
        u.z = *reinterpret_cast<uint32_t*>(&h2);
        u.w = *reinterpret_cast<uint32_t*>(&h3);
        g_xfrag[(size_t)f * 32 + lane] = u;
    } else {
        // B pack: tile 32 n x 64 k, 8 warps -> 8 fragments (2 nb x 4 kb)
        __shared__ float ws[64][33];   // ws[k][n] = w[k0+k][n0+n]
        int bb = blockIdx.x - CONV_BLOCKS;
        int n0 = (bb / BPACK_KT) * 32;
        int k0 = (bb % BPACK_KT) * 64;
        int t = threadIdx.x;
        {
            int j = t & 31;        // n
            int i0 = t >> 5;       // k start
#pragma unroll
            for (int it = 0; it < 8; ++it)
                ws[i0 + 8 * it][j] = w[(size_t)(k0 + i0 + 8 * it) * NDIM + (n0 + j)];
        }
        __syncthreads();
        int q = t >> 5;            // warp 0..7
        int lane = t & 31;
        int kbq = q & 3;           // k 16-block within tile
        int nbq = q >> 2;          // n 16-block within tile
        int nn = nbq * 16 + (lane >> 2);      // local n (0..31)
        int kk = kbq * 16 + (lane & 3) * 2;   // local k (0..63)
        const float* gm = mask + (size_t)(n0 + nn) * KDIM + (k0 + kk);
        float2 m00 = *reinterpret_cast<const float2*>(gm);
        float2 m01 = *reinterpret_cast<const float2*>(gm + 8);
        float2 m10 = *reinterpret_cast<const float2*>(gm + (size_t)8 * KDIM);
        float2 m11 = *reinterpret_cast<const float2*>(gm + (size_t)8 * KDIM + 8);
        __half2 hx = __floats2half2_rn(m00.x * ws[kk][nn],     m00.y * ws[kk + 1][nn]);
        __half2 hy = __floats2half2_rn(m01.x * ws[kk + 8][nn], m01.y * ws[kk + 9][nn]);
        __half2 hz = __floats2half2_rn(m10.x * ws[kk][nn + 8],     m10.y * ws[kk + 1][nn + 8]);
        __half2 hw = __floats2half2_rn(m11.x * ws[kk + 8][nn + 8], m11.y * ws[kk + 9][nn + 8]);
        uint4 u;
        u.x = *reinterpret_cast<uint32_t*>(&hx);
        u.y = *reinterpret_cast<uint32_t*>(&hy);
        u.z = *reinterpret_cast<uint32_t*>(&hz);
        u.w = *reinterpret_cast<uint32_t*>(&hw);
        int nb = (n0 >> 4) + nbq;
        int kbg = (k0 >> 4) + kbq;
        g_Bfrag[((size_t)nb * KB16 + kbg) * 32 + lane] = u;
    }
}

// ---------------------------------------------------------------------------
// GEMM. CTA 256x64, 8 warps each 32(M)x64(N). Pure LDG+MMA, no smem.
// Structural-zero 16-k blocks skipped; LPT tile order.
// ---------------------------------------------------------------------------
__global__ void __launch_bounds__(256, 2) gemm_f16_kernel(const float* __restrict__ bias,
                                                          float* __restrict__ out) {
    const int tid = threadIdx.x;
    const int wid = tid >> 5;      // 0..7 -> rows wid*32 .. +31
    const int lane = tid & 31;

    // LPT tile mapping: long tiles (ub1: tn in [8,16)) first.
    int tm, tn;
    if (blockIdx.x < 256) {
        tm = blockIdx.x >> 3;
        tn = 8 + (blockIdx.x & 7);
    } else {
        int idx = blockIdx.x - 256;
        tm = idx >> 4;
        int r = idx & 15;
        tn = (r < 8) ? r : (8 + r);
    }
    const int m0 = tm * TM;
    const int n0 = tn * TN;

    // Structural-zero skipping over 16-k blocks.
    //   ub0: blocks [0,64) u [96,160)  -> 128 iters
    //   ub1: blocks [0,192)            -> 192 iters
    //   ub2: blocks [32,96) u [128,192)-> 128 iters
    const int ub = n0 >> 9;
    const int niter  = (ub == 1) ? 192 : 128;
    const int kbase  = (ub == 2) ? 32 : 0;
    const int thresh = (ub == 1) ? 192 : 64;
#define KB(i) ((i) + kbase + (((i) >= thresh) ? 32 : 0))

    float acc[2][8][4];
#pragma unroll
    for (int i = 0; i < 2; ++i)
#pragma unroll
        for (int j = 0; j < 8; ++j)
#pragma unroll
            for (int q = 0; q < 4; ++q) acc[i][j][q] = 0.0f;

    // Fragment base pointers (per lane). Constant strides fold into LDG imms.
    const uint4* ap = g_xfrag + ((size_t)(m0 / 16 + wid * 2) * KB16) * 32 + lane;
    const uint4* bp = g_Bfrag + ((size_t)(n0 >> 4) * KB16) * 32 + lane;
    const size_t MSTR = (size_t)KB16 * 32;   // one 16-row block stride (uint4s)

    uint4 af[2][2];   // [buf][mt]
    uint4 bf[2][4];   // [buf][g]

    // Prologue: load kb(0)
    {
        const size_t o = (size_t)KB(0) * 32;
        af[0][0] = ap[o];
        af[0][1] = ap[o + MSTR];
        bf[0][0] = bp[o];
        bf[0][1] = bp[o + MSTR];
        bf[0][2] = bp[o + 2 * MSTR];
        bf[0][3] = bp[o + 3 * MSTR];
    }

#pragma unroll 2
    for (int j = 0; j < niter; ++j) {
        const int cur = j & 1;
        const int nxt = cur ^ 1;
        if (j + 1 < niter) {
            const size_t o = (size_t)KB(j + 1) * 32;
            af[nxt][0] = ap[o];
            af[nxt][1] = ap[o + MSTR];
            bf[nxt][0] = bp[o];
            bf[nxt][1] = bp[o + MSTR];
            bf[nxt][2] = bp[o + 2 * MSTR];
            bf[nxt][3] = bp[o + 3 * MSTR];
        }
#pragma unroll
        for (int mt = 0; mt < 2; ++mt) {
            const uint4 a = af[cur][mt];
#pragma unroll
            for (int nt = 0; nt < 8; ++nt) {
                const uint4 bv = bf[cur][nt >> 1];
                const uint32_t b0 = (nt & 1) ? bv.z : bv.x;
                const uint32_t b1 = (nt & 1) ? bv.w : bv.y;
                MMA16816(acc[mt][nt], a.x, a.y, a.z, a.w, b0, b1);
            }
        }
    }
#undef KB

    // Epilogue: direct global stores + bias
    const int grp = lane >> 2, tig = lane & 3;
#pragma unroll
    for (int mt = 0; mt < 2; ++mt) {
        const int row0 = m0 + wid * 32 + mt * 16 + grp;
#pragma unroll
        for (int nt = 0; nt < 8; ++nt) {
            const int col = n0 + nt * 8 + tig * 2;
            const float2 bb = *reinterpret_cast<const float2*>(bias + col);
            float2 v0, v1;
            v0.x = acc[mt][nt][0] + bb.x;
            v0.y = acc[mt][nt][1] + bb.y;
            v1.x = acc[mt][nt][2] + bb.x;
            v1.y = acc[mt][nt][3] + bb.y;
            *reinterpret_cast<float2*>(out + (size_t)row0 * NDIM + col) = v0;
            *reinterpret_cast<float2*>(out + (size_t)(row0 + 8) * NDIM + col) = v1;
        }
    }
}

// ---------------------------------------------------------------------------
// Launch
// ---------------------------------------------------------------------------
extern "C" void kernel_launch(void* const* d_in, const int* in_sizes, int n_in,
                              void* d_out, int out_size) {
    const float* x    = (const float*)d_in[0];   // [8192, 3072]
    const float* w    = (const float*)d_in[1];   // [3072, 1536]
    const float* b    = (const float*)d_in[2];   // [1536]
    const float* mask = (const float*)d_in[3];   // [1536, 3072]
    float* out = (float*)d_out;                  // [8192, 1536]

    // 1) Fused prep: A fragments + B fragments
    prep_kernel<<<CONV_BLOCKS + BPACK_BLOCKS, 256>>>(x, w, mask);

    // 2) Smem-free GEMM
    gemm_f16_kernel<<<TILES_M * TILES_N, 256>>>(b, out);
}

// round 15
// speedup vs baseline: 1.0970x; 1.0970x over previous
#include <cuda_runtime.h>
#include <cuda_fp16.h>
#include <cstdint>

// ============================================================================
// out[8192,1536] = x[8192,3072] @ (mask.T * w)[3072,1536] + b
// R15: R13 base (best: A frags via LDG, B via cp.async+LDSM, B-frag double
//      buffering) with 256-k pipeline chunks (barrier frequency halved again;
//      3 stages x 32KB, 2 CTA/SM).
// ============================================================================

static constexpr int MDIM = 8192;
static constexpr int NDIM = 1536;
static constexpr int KDIM = 3072;

static constexpr int TM = 256;
static constexpr int TN = 64;
static constexpr int TKC = 256;             // halves per pipeline chunk (4 k-tiles)
static constexpr int STAGES = 3;
static constexpr int TILES_N = NDIM / TN;   // 24
static constexpr int TILES_M = MDIM / TM;   // 32
static constexpr int KB16 = KDIM / 16;      // 192 16-k fragment blocks

static constexpr int SUB_BYTES = TN * 64 * 2;           // 8192 (one 64-k sub-tile)
static constexpr int STAGE_BYTES = 4 * SUB_BYTES;       // 32768
static constexpr int SMEM_TOTAL = STAGES * STAGE_BYTES; // 98304 -> 2 CTAs/SM

// Prep kernel grid split
static constexpr int CONV_BLOCKS = (MDIM / 16) * KB16 / 8;        // 12288
static constexpr int PREPB_BLOCKS = (KDIM / 32) * (NDIM / 32);    // 4608

// A in fragment-major layout: frag (mb, kb) -> 32 lanes x 16B
__device__ uint4  g_xfrag[(size_t)(MDIM / 16) * KB16 * 32];
__device__ __half g_Bh[(size_t)NDIM * KDIM];   // 9.4 MB, [n][k]

// ---------------------------------------------------------------------------
// PTX helpers
// ---------------------------------------------------------------------------
__device__ __forceinline__ uint32_t smem_u32(const void* p) {
    uint32_t a;
    asm("{ .reg .u64 t; cvta.to.shared.u64 t, %1; cvt.u32.u64 %0, t; }" : "=r"(a) : "l"(p));
    return a;
}

#define CP_ASYNC16(dst, src) \
    asm volatile("cp.async.cg.shared.global [%0], [%1], 16;" :: "r"(dst), "l"(src) : "memory")
#define CP_COMMIT() asm volatile("cp.async.commit_group;" ::: "memory")
#define CP_WAIT1()  asm volatile("cp.async.wait_group 1;" ::: "memory")

#define LDSM_X4(r0, r1, r2, r3, addr) \
    asm volatile("ldmatrix.sync.aligned.m8n8.x4.shared.b16 {%0,%1,%2,%3}, [%4];" \
                 : "=r"(r0), "=r"(r1), "=r"(r2), "=r"(r3) : "r"(addr))

#define MMA16816(d, a0, a1, a2, a3, b0, b1) \
    asm volatile("mma.sync.aligned.m16n8k16.row.col.f32.f16.f16.f32 " \
                 "{%0,%1,%2,%3}, {%4,%5,%6,%7}, {%8,%9}, {%0,%1,%2,%3};" \
                 : "+f"((d)[0]), "+f"((d)[1]), "+f"((d)[2]), "+f"((d)[3]) \
                 : "r"(a0), "r"(a1), "r"(a2), "r"(a3), "r"(b0), "r"(b1))

// ---------------------------------------------------------------------------
// Fused prep kernel
// ---------------------------------------------------------------------------
__global__ void __launch_bounds__(256) prep_kernel(const float* __restrict__ x,
                                                   const float* __restrict__ w,
                                                   const float* __restrict__ mask) {
    if (blockIdx.x < CONV_BLOCKS) {
        int f = blockIdx.x * 8 + (threadIdx.x >> 5);   // fragment id
        int lane = threadIdx.x & 31;
        int mb = f / KB16;
        int kb = f - mb * KB16;
        int r = mb * 16 + (lane >> 2);
        int c = kb * 16 + (lane & 3) * 2;
        const float* p00 = x + (size_t)r * KDIM + c;
        float2 v00 = *reinterpret_cast<const float2*>(p00);
        float2 v10 = *reinterpret_cast<const float2*>(p00 + 8 * KDIM);
        float2 v01 = *reinterpret_cast<const float2*>(p00 + 8);
        float2 v11 = *reinterpret_cast<const float2*>(p00 + 8 * KDIM + 8);
        __half2 h0 = __floats2half2_rn(v00.x, v00.y);
        __half2 h1 = __floats2half2_rn(v10.x, v10.y);
        __half2 h2 = __floats2half2_rn(v01.x, v01.y);
        __half2 h3 = __floats2half2_rn(v11.x, v11.y);
        uint4 u;
        u.x = *reinterpret_cast<uint32_t*>(&h0);
        u.y = *reinterpret_cast<uint32_t*>(&h1);
        u.z = *reinterpret_cast<uint32_t*>(&h2);
        u.w = *reinterpret_cast<uint32_t*>(&h3);
        g_xfrag[(size_t)f * 32 + lane] = u;
    } else {
        __shared__ float ws[32][33];
        int bb = blockIdx.x - CONV_BLOCKS;
        int k0 = (bb % (KDIM / 32)) * 32;
        int n0 = (bb / (KDIM / 32)) * 32;
        int tx = threadIdx.x & 31;
        int ty = threadIdx.x >> 5;
#pragma unroll
        for (int i = 0; i < 32; i += 8)
            ws[ty + i][tx] = w[(size_t)(k0 + ty + i) * NDIM + (n0 + tx)];
        __syncthreads();
#pragma unroll
        for (int i = 0; i < 32; i += 8) {
            int n = n0 + ty + i;
            int k = k0 + tx;
            size_t idx = (size_t)n * KDIM + k;
            g_Bh[idx] = __float2half(mask[idx] * ws[tx][ty + i]);
        }
    }
}

// ---------------------------------------------------------------------------
// GEMM. CTA 256x64, 8 warps each 32(M)x64(N). A via LDG.128 of pre-packed
// fragments (pairwise, distance 2); B via 3-stage cp.async (256-k chunks)
// + per-ks double-buffered LDSM. Structural-zero chunks skipped; LPT order.
// ---------------------------------------------------------------------------
__global__ void __launch_bounds__(256, 2) gemm_f16_kernel(const float* __restrict__ bias,
                                                          float* __restrict__ out) {
    extern __shared__ char smem[];
    const uint32_t sbase = smem_u32(smem);
    const int tid = threadIdx.x;
    const int wid = tid >> 5;      // 0..7 -> rows wid*32 .. +31
    const int lane = tid & 31;

    // LPT tile mapping: long tiles (ub1: tn in [8,16)) first.
    int tm, tn;
    if (blockIdx.x < 256) {
        tm = blockIdx.x >> 3;
        tn = 8 + (blockIdx.x & 7);
    } else {
        int idx = blockIdx.x - 256;
        tm = idx >> 4;
        int r = idx & 15;
        tn = (r < 8) ? r : (8 + r);
    }
    const int m0 = tm * TM;
    const int n0 = tn * TN;

    // Structural-zero skipping over 256-wide k-chunks.
    //   ub0: chunks [0,4) u [6,10)   -> 8 iters, kc = i + (i>=4)*2
    //   ub1: chunks [0,12)           -> 12 iters, kc = i
    //   ub2: chunks [2,6) u [8,12)   -> 8 iters, kc = i + 2 + (i>=4)*2
    const int ub = n0 >> 9;
    const int niter  = (ub == 1) ? 12 : 8;
    const int kbase  = (ub == 2) ? 2 : 0;
    const int thresh = (ub == 1) ? 12 : 4;
#define KCHUNK(i) ((i) + kbase + (((i) >= thresh) ? 2 : 0))

    float acc[2][8][4];
#pragma unroll
    for (int i = 0; i < 2; ++i)
#pragma unroll
        for (int j = 0; j < 8; ++j)
#pragma unroll
            for (int q = 0; q < 4; ++q) acc[i][j][q] = 0.0f;

    // B chunk loader: 4 sub-tiles x (64 rows x 128 B); 2048 16B chunks, 8/thread
    const __half* bbase_g = g_Bh + (size_t)n0 * KDIM;
    auto load_B = [&](int s, int kc) {
        uint32_t sa = sbase + s * STAGE_BYTES;
#pragma unroll
        for (int sub = 0; sub < 4; ++sub) {
            const __half* ba = bbase_g + kc * TKC + sub * 64;
            uint32_t dsub = sa + sub * SUB_BYTES;
#pragma unroll
            for (int i = 0; i < 2; ++i) {
                int c = tid + i * 256;
                int row = c >> 3, q = c & 7;
                uint32_t dst = dsub + row * 128 + ((q ^ (row & 7)) << 4);
                CP_ASYNC16(dst, ba + (size_t)row * KDIM + q * 8);
            }
        }
    };

#pragma unroll
    for (int s = 0; s < STAGES - 1; ++s) {
        load_B(s, KCHUNK(s));
        CP_COMMIT();
    }

    // A fragment bases
    const uint4* afrag0 = g_xfrag + ((size_t)(m0 / 16 + wid * 2 + 0) * KB16) * 32 + lane;
    const uint4* afrag1 = g_xfrag + ((size_t)(m0 / 16 + wid * 2 + 1) * KB16) * 32 + lane;

    // B ldmatrix per-lane selectors
    const int b_rowsel = ((lane >> 4) << 3) + (lane & 7);  // + g*16
    const int b_chunksel = (lane >> 3) & 1;                // + (ks&3)*2

    uint4 af[2][4];         // [pair buf][ks_in_pair*2 + mt]
    uint32_t bf[2][4][4];   // [ks buf][g][frag]

    auto load_bf = [&](int buf, uint32_t bBase, int ks) {
        const uint32_t subBase = bBase + (ks >> 2) * SUB_BYTES;
        const int chunk = (ks & 3) * 2 + b_chunksel;
#pragma unroll
        for (int g = 0; g < 4; ++g) {
            int row = g * 16 + b_rowsel;
            uint32_t addr = subBase + row * 128 + ((chunk ^ (row & 7)) << 4);
            LDSM_X4(bf[buf][g][0], bf[buf][g][1], bf[buf][g][2], bf[buf][g][3], addr);
        }
    };

    int stage = 0;
    for (int j = 0; j < niter; ++j) {
        const int kb0 = KCHUNK(j) * 16;  // first 16-k fragment block of chunk
        // A: prefetch pair 0 (ks 0,1) before the wait to cover L2 latency
        af[0][0] = afrag0[(size_t)(kb0 + 0) * 32];
        af[0][1] = afrag1[(size_t)(kb0 + 0) * 32];
        af[0][2] = afrag0[(size_t)(kb0 + 1) * 32];
        af[0][3] = afrag1[(size_t)(kb0 + 1) * 32];

        CP_WAIT1();
        __syncthreads();

        const int jn = j + STAGES - 1;
        if (jn < niter) {
            int sn = stage + 2;
            if (sn >= STAGES) sn -= STAGES;
            load_B(sn, KCHUNK(jn));
        }
        CP_COMMIT();

        const uint32_t bBase = sbase + stage * STAGE_BYTES;
        if (++stage == STAGES) stage = 0;

        // B: prefetch ks=0 into buffer 0 (single refill point per chunk)
        load_bf(0, bBase, 0);

#pragma unroll
        for (int ks = 0; ks < 16; ++ks) {
            const int cb = ks & 1;          // current B buffer
            const int ap = (ks >> 1) & 1;   // current A pair buffer
            if ((ks & 1) == 0 && ks < 14) {
                const int kn = kb0 + ks + 2;
                af[ap ^ 1][0] = afrag0[(size_t)(kn + 0) * 32];
                af[ap ^ 1][1] = afrag1[(size_t)(kn + 0) * 32];
                af[ap ^ 1][2] = afrag0[(size_t)(kn + 1) * 32];
                af[ap ^ 1][3] = afrag1[(size_t)(kn + 1) * 32];
            }
            if (ks < 15) load_bf(cb ^ 1, bBase, ks + 1);

            const int ai = (ks & 1) * 2;
#pragma unroll
            for (int mt = 0; mt < 2; ++mt)
#pragma unroll
                for (int nt = 0; nt < 8; ++nt) {
                    const uint32_t b0 = bf[cb][nt >> 1][(nt & 1) * 2 + 0];
                    const uint32_t b1 = bf[cb][nt >> 1][(nt & 1) * 2 + 1];
                    MMA16816(acc[mt][nt], af[ap][ai + mt].x, af[ap][ai + mt].y,
                             af[ap][ai + mt].z, af[ap][ai + mt].w, b0, b1);
                }
        }
    }
#undef KCHUNK

    // Epilogue
    const int grp = lane >> 2, tig = lane & 3;
#pragma unroll
    for (int mt = 0; mt < 2; ++mt) {
        const int row0 = m0 + wid * 32 + mt * 16 + grp;
#pragma unroll
        for (int nt = 0; nt < 8; ++nt) {
            const int col = n0 + nt * 8 + tig * 2;
            const float2 bb = *reinterpret_cast<const float2*>(bias + col);
            float2 v0, v1;
            v0.x = acc[mt][nt][0] + bb.x;
            v0.y = acc[mt][nt][1] + bb.y;
            v1.x = acc[mt][nt][2] + bb.x;
            v1.y = acc[mt][nt][3] + bb.y;
            *reinterpret_cast<float2*>(out + (size_t)row0 * NDIM + col) = v0;
            *reinterpret_cast<float2*>(out + (size_t)(row0 + 8) * NDIM + col) = v1;
        }
    }
}

// ---------------------------------------------------------------------------
// Launch
// ---------------------------------------------------------------------------
extern "C" void kernel_launch(void* const* d_in, const int* in_sizes, int n_in,
                              void* d_out, int out_size) {
    const float* x    = (const float*)d_in[0];   // [8192, 3072]
    const float* w    = (const float*)d_in[1];   // [3072, 1536]
    const float* b    = (const float*)d_in[2];   // [1536]
    const float* mask = (const float*)d_in[3];   // [1536, 3072]
    float* out = (float*)d_out;                  // [8192, 1536]

    // 1) Fused prep
    prep_kernel<<<CONV_BLOCKS + PREPB_BLOCKS, 256>>>(x, w, mask);

    // 2) GEMM
    cudaFuncSetAttribute(gemm_f16_kernel, cudaFuncAttributeMaxDynamicSharedMemorySize,
                         SMEM_TOTAL);
    gemm_f16_kernel<<<TILES_M * TILES_N, 256, SMEM_TOTAL>>>(b, out);
}